// round 12
// baseline (speedup 1.0000x reference)
#include <cuda_runtime.h>
#include <cuda_bf16.h>

// Problem constants (fixed by setup_inputs):
// x_0  : [128, 64, 16] f32   (d_in[0])
// x_h  : [128, 64, 16] f32   (d_in[1], UNUSED — reference bug recomputes from x_0)
// Vm   : [64, 1, 64, 16] f32 (d_in[2])
// Vh   : [64, 1, 16, 64] f32 (d_in[3])
// out  : [128, 64, 16] f32
//
// out[b,k,d] = sum_v P[n,kv] * Q[n,kv] summed over v, n = b*16+d, kv = k*16+v
//   P[n,kv] = sum_i x0[b,i,d]        * Vm[k,i,v]
//   Q[n,kv] = sum_j x0flat[b,64d+j]  * Vh[k,v,j]
//
// R12: tensor-core path. Each GEMM done in bf16 with 3-term error compensation
// folded into the K dimension: A = [hi|lo|hi] (K=192), B = [whi|whi|wlo]
// -> A*B = hi*whi + lo*whi + hi*wlo  (residual ~2^-18, rel_err ~1e-5).
// CTA tile = 64 n-rows x 64 kv-cols (4 k). 4 warps, warp = 16 rows.
// mma.sync.aligned.m16n8k16.row.col.f32.bf16.bf16.f32 (fallback HMMA).

#define NTHR 128
#define XROW 200      // padded row stride (bf16) for X and W tiles (conflict-free frags)
#define PROW 72       // padded row stride (f32) for P stash

// smem: Xs 64*200*2 = 25600 B; Ws 25600 B; Ps 64*72*4 = 18432 B
#define OFF_X 0
#define OFF_W 25600
#define OFF_P 51200
#define SMEM_BYTES 69632

__device__ __forceinline__ void mma_bf16(float c[4],
        unsigned a0, unsigned a1, unsigned a2, unsigned a3,
        unsigned b0, unsigned b1) {
    asm volatile(
        "mma.sync.aligned.m16n8k16.row.col.f32.bf16.bf16.f32 "
        "{%0,%1,%2,%3},{%4,%5,%6,%7},{%8,%9},{%0,%1,%2,%3};"
        : "+f"(c[0]), "+f"(c[1]), "+f"(c[2]), "+f"(c[3])
        : "r"(a0), "r"(a1), "r"(a2), "r"(a3), "r"(b0), "r"(b1));
}

__global__ void __launch_bounds__(NTHR, 3)
cin_tc_kernel(const float* __restrict__ x0,
              const float* __restrict__ Vm,
              const float* __restrict__ Vh,
              float* __restrict__ out)
{
    extern __shared__ __align__(16) unsigned char smem[];
    __nv_bfloat16* Xs = reinterpret_cast<__nv_bfloat16*>(smem + OFF_X);
    __nv_bfloat16* Ws = reinterpret_cast<__nv_bfloat16*>(smem + OFF_W);
    float*         Ps = reinterpret_cast<float*>(smem + OFF_P);

    const int tid   = threadIdx.x;
    const int k0    = blockIdx.x * 4;    // 16 kv-tiles (4 k each)
    const int ntile = blockIdx.y * 64;   // 32 n-tiles

    // ---- phase A staging: Xa[n][i] = x0[b,i,d]; Wm[c][i] = Vm[k,i,v] ----
    #pragma unroll
    for (int r = 0; r < 32; r++) {
        int idx = tid + r * NTHR;        // 0..4095
        int n = idx >> 6, i = idx & 63;
        int ng = ntile + n;
        float xv = x0[(ng >> 4) * 1024 + i * 16 + (ng & 15)];
        __nv_bfloat16 xhi = __float2bfloat16(xv);
        __nv_bfloat16 xlo = __float2bfloat16(xv - __bfloat162float(xhi));
        Xs[n * XROW + i]       = xhi;    // [hi | lo | hi]
        Xs[n * XROW + 64 + i]  = xlo;
        Xs[n * XROW + 128 + i] = xhi;
        float wv = Vm[(k0 + (n >> 4)) * 1024 + i * 16 + (n & 15)];
        __nv_bfloat16 whi = __float2bfloat16(wv);
        __nv_bfloat16 wlo = __float2bfloat16(wv - __bfloat162float(whi));
        Ws[n * XROW + i]       = whi;    // [whi | whi | wlo]
        Ws[n * XROW + 64 + i]  = whi;
        Ws[n * XROW + 128 + i] = wlo;
    }
    __syncthreads();

    const int w    = tid >> 5;
    const int lane = tid & 31;
    const int g    = lane >> 2;   // 0..7  (fragment row / B col)
    const int q    = lane & 3;    // 0..3  (fragment k-pair / col pair)
    const int rA   = w * 16 + g;  // this thread's low row within the 64-row tile

    // ---- GEMM A: P = Xa * Wm^T ----
    float cf[8][4];
    #pragma unroll
    for (int j = 0; j < 8; j++)
        #pragma unroll
        for (int p = 0; p < 4; p++) cf[j][p] = 0.f;

    #pragma unroll
    for (int ks = 0; ks < 12; ks++) {
        const int kc = ks * 16 + 2 * q;
        unsigned a0 = *reinterpret_cast<const unsigned*>(&Xs[rA * XROW + kc]);
        unsigned a1 = *reinterpret_cast<const unsigned*>(&Xs[(rA + 8) * XROW + kc]);
        unsigned a2 = *reinterpret_cast<const unsigned*>(&Xs[rA * XROW + kc + 8]);
        unsigned a3 = *reinterpret_cast<const unsigned*>(&Xs[(rA + 8) * XROW + kc + 8]);
        #pragma unroll
        for (int j = 0; j < 8; j++) {
            unsigned b0 = *reinterpret_cast<const unsigned*>(&Ws[(j * 8 + g) * XROW + kc]);
            unsigned b1 = *reinterpret_cast<const unsigned*>(&Ws[(j * 8 + g) * XROW + kc + 8]);
            mma_bf16(cf[j], a0, a1, a2, a3, b0, b1);
        }
    }

    // ---- stash P to smem ----
    #pragma unroll
    for (int j = 0; j < 8; j++) {
        int cbase = j * 8 + 2 * q;
        Ps[rA * PROW + cbase]           = cf[j][0];
        Ps[rA * PROW + cbase + 1]       = cf[j][1];
        Ps[(rA + 8) * PROW + cbase]     = cf[j][2];
        Ps[(rA + 8) * PROW + cbase + 1] = cf[j][3];
    }
    __syncthreads();   // all GEMM_A reads of Xs/Ws done; safe to restage

    // ---- phase B staging: Xb[n][j] = x0flat[b,64d+j]; Wh[c][j] = Vh[k,v,j] ----
    #pragma unroll
    for (int r = 0; r < 32; r++) {
        int idx = tid + r * NTHR;
        int n = idx >> 6, j = idx & 63;
        int ng = ntile + n;
        float xv = x0[(ng >> 4) * 1024 + (ng & 15) * 64 + j];
        __nv_bfloat16 xhi = __float2bfloat16(xv);
        __nv_bfloat16 xlo = __float2bfloat16(xv - __bfloat162float(xhi));
        Xs[n * XROW + j]       = xhi;
        Xs[n * XROW + 64 + j]  = xlo;
        Xs[n * XROW + 128 + j] = xhi;
        float wv = Vh[(k0 + (n >> 4)) * 1024 + (n & 15) * 64 + j];
        __nv_bfloat16 whi = __float2bfloat16(wv);
        __nv_bfloat16 wlo = __float2bfloat16(wv - __bfloat162float(whi));
        Ws[n * XROW + j]       = whi;
        Ws[n * XROW + 64 + j]  = whi;
        Ws[n * XROW + 128 + j] = wlo;
    }
    __syncthreads();

    // ---- GEMM B: Q = Xb * Wh^T ----
    float cq[8][4];
    #pragma unroll
    for (int j = 0; j < 8; j++)
        #pragma unroll
        for (int p = 0; p < 4; p++) cq[j][p] = 0.f;

    #pragma unroll
    for (int ks = 0; ks < 12; ks++) {
        const int kc = ks * 16 + 2 * q;
        unsigned a0 = *reinterpret_cast<const unsigned*>(&Xs[rA * XROW + kc]);
        unsigned a1 = *reinterpret_cast<const unsigned*>(&Xs[(rA + 8) * XROW + kc]);
        unsigned a2 = *reinterpret_cast<const unsigned*>(&Xs[rA * XROW + kc + 8]);
        unsigned a3 = *reinterpret_cast<const unsigned*>(&Xs[(rA + 8) * XROW + kc + 8]);
        #pragma unroll
        for (int j = 0; j < 8; j++) {
            unsigned b0 = *reinterpret_cast<const unsigned*>(&Ws[(j * 8 + g) * XROW + kc]);
            unsigned b1 = *reinterpret_cast<const unsigned*>(&Ws[(j * 8 + g) * XROW + kc + 8]);
            mma_bf16(cq[j], a0, a1, a2, a3, b0, b1);
        }
    }

    // ---- dot: out[n,k] = sum_v P*Q; v-group = 16 cols = 2 fragment blocks ----
    float sl[4] = {0.f, 0.f, 0.f, 0.f};
    float sh[4] = {0.f, 0.f, 0.f, 0.f};
    #pragma unroll
    for (int j = 0; j < 8; j++) {
        int kg = j >> 1;
        int cbase = j * 8 + 2 * q;
        float p0 = Ps[rA * PROW + cbase];
        float p1 = Ps[rA * PROW + cbase + 1];
        float p2 = Ps[(rA + 8) * PROW + cbase];
        float p3 = Ps[(rA + 8) * PROW + cbase + 1];
        sl[kg] = fmaf(cq[j][0], p0, fmaf(cq[j][1], p1, sl[kg]));
        sh[kg] = fmaf(cq[j][2], p2, fmaf(cq[j][3], p3, sh[kg]));
    }
    #pragma unroll
    for (int kg = 0; kg < 4; kg++) {
        sl[kg] += __shfl_xor_sync(0xffffffffu, sl[kg], 1);
        sl[kg] += __shfl_xor_sync(0xffffffffu, sl[kg], 2);
        sh[kg] += __shfl_xor_sync(0xffffffffu, sh[kg], 1);
        sh[kg] += __shfl_xor_sync(0xffffffffu, sh[kg], 2);
    }
    if (q == 0) {
        int nlo = ntile + rA;
        int nhi = nlo + 8;
        #pragma unroll
        for (int kg = 0; kg < 4; kg++) {
            int k = k0 + kg;
            out[(nlo >> 4) * 1024 + k * 16 + (nlo & 15)] = sl[kg];
            out[(nhi >> 4) * 1024 + k * 16 + (nhi & 15)] = sh[kg];
        }
    }
}

extern "C" void kernel_launch(void* const* d_in, const int* in_sizes, int n_in,
                              void* d_out, int out_size) {
    (void)in_sizes; (void)n_in; (void)out_size;
    const float* x0 = (const float*)d_in[0];
    // d_in[1] (x_h) intentionally unused: reference recomputes it from x_0.
    const float* Vm = (const float*)d_in[2];
    const float* Vh = (const float*)d_in[3];
    float* out = (float*)d_out;

    cudaFuncSetAttribute(cin_tc_kernel,
                         cudaFuncAttributeMaxDynamicSharedMemorySize, SMEM_BYTES);

    dim3 grid(16, 32);   // (kv-tiles of 64 cols, n-tiles of 64 rows) = 512 CTAs
    cin_tc_kernel<<<grid, NTHR, SMEM_BYTES>>>(x0, Vm, Vh, out);
}

// round 13
// speedup vs baseline: 1.6245x; 1.6245x over previous
#include <cuda_runtime.h>
#include <cuda_bf16.h>

// Problem constants (fixed by setup_inputs):
// x_0  : [128, 64, 16] f32   (d_in[0])
// x_h  : [128, 64, 16] f32   (d_in[1], UNUSED — reference bug recomputes from x_0)
// Vm   : [64, 1, 64, 16] f32 (d_in[2])
// Vh   : [64, 1, 16, 64] f32 (d_in[3])
// out  : [128, 64, 16] f32
//
// out[b,k,d] = sum_v P[n,kv]*Q[n,kv], n = b*16+d, kv = k*16+v
//   P = Xa[2048x64] * Wm^T,  Q = Xb[2048x64] * Wh^T
// bf16 3-term split folded into K: A=[hi|lo|hi] (K=192), B=[whi|whi|wlo]
// -> A*B = x*w - lo_x*lo_w  (rel err ~2^-16).
//
// R13: prep kernel converts/transposes ONCE into global composite matrices;
// GEMM kernel: contiguous uint4 staging + ldmatrix.x4 + HMMA + in-register dot.

#define CW 192           // composite K width (bf16)
#define NROWS 2048
#define KVROWS 1024
#define XROWB 400        // padded smem row stride in bytes (200 bf16)

__device__ __nv_bfloat16 g_XaC[NROWS * CW];
__device__ __nv_bfloat16 g_XbC[NROWS * CW];
__device__ __nv_bfloat16 g_WmC[KVROWS * CW];
__device__ __nv_bfloat16 g_WhC[KVROWS * CW];

// ============================ prep kernel ============================
// blocks 0..127: X prep for b=bid. blocks 128..191: Wm k=bid-128.
// blocks 192..255: Wh k=bid-192. Each loads one 1024-float tile into
// padded smem, then emits 16 rows x 192 bf16 per output array.
__global__ void __launch_bounds__(128)
prep_kernel(const float* __restrict__ x0,
            const float* __restrict__ Vm,
            const float* __restrict__ Vh)
{
    __shared__ float sp[64 * 17 + 17];
    const int tid = threadIdx.x;
    const int bid = blockIdx.x;

    const float* src;
    if (bid < 128)      src = x0 + bid * 1024;
    else if (bid < 192) src = Vm + (bid - 128) * 1024;
    else                src = Vh + (bid - 192) * 1024;

    const float4* s4 = reinterpret_cast<const float4*>(src);
    #pragma unroll
    for (int e = 0; e < 2; e++) {
        int f4 = tid + e * 128;
        float4 wv = s4[f4];
        int f = f4 * 4;                       // f = i*16 + d  (d multiple of 4)
        float* dst = &sp[(f >> 4) * 17 + (f & 15)];
        dst[0] = wv.x; dst[1] = wv.y; dst[2] = wv.z; dst[3] = wv.w;
    }
    __syncthreads();

    const int r  = tid >> 3;          // d (X) or v (W), 0..15
    const int cb = (tid & 7) * 24;    // 24 consecutive c per thread

    if (bid < 128) {
        const int n = bid * 16 + r;
        unsigned ua[12], ub[12];
        #pragma unroll
        for (int p = 0; p < 12; p++) {
            unsigned short ha[2], hb[2];
            #pragma unroll
            for (int e = 0; e < 2; e++) {
                int c   = cb + p * 2 + e;
                int seg = c >> 6;             // 0: hi, 1: lo, 2: hi
                int idx = c & 63;
                // Xa: x0[b, i=idx, d=r]
                float va = sp[idx * 17 + r];
                __nv_bfloat16 hia = __float2bfloat16(va);
                ha[e] = (seg == 1)
                    ? __bfloat16_as_ushort(__float2bfloat16(va - __bfloat162float(hia)))
                    : __bfloat16_as_ushort(hia);
                // Xb: x0flat[b, d*64 + j], j=idx
                int f = r * 64 + idx;
                float vb = sp[(f >> 4) * 17 + (f & 15)];
                __nv_bfloat16 hib = __float2bfloat16(vb);
                hb[e] = (seg == 1)
                    ? __bfloat16_as_ushort(__float2bfloat16(vb - __bfloat162float(hib)))
                    : __bfloat16_as_ushort(hib);
            }
            ua[p] = (unsigned)ha[0] | ((unsigned)ha[1] << 16);
            ub[p] = (unsigned)hb[0] | ((unsigned)hb[1] << 16);
        }
        uint4* da = reinterpret_cast<uint4*>(g_XaC + n * CW + cb);
        da[0] = make_uint4(ua[0], ua[1], ua[2],  ua[3]);
        da[1] = make_uint4(ua[4], ua[5], ua[6],  ua[7]);
        da[2] = make_uint4(ua[8], ua[9], ua[10], ua[11]);
        uint4* db = reinterpret_cast<uint4*>(g_XbC + n * CW + cb);
        db[0] = make_uint4(ub[0], ub[1], ub[2],  ub[3]);
        db[1] = make_uint4(ub[4], ub[5], ub[6],  ub[7]);
        db[2] = make_uint4(ub[8], ub[9], ub[10], ub[11]);
    } else {
        const bool isWm = bid < 192;
        const int k  = isWm ? (bid - 128) : (bid - 192);
        const int kv = k * 16 + r;        // r = v
        unsigned uw[12];
        #pragma unroll
        for (int p = 0; p < 12; p++) {
            unsigned short hw[2];
            #pragma unroll
            for (int e = 0; e < 2; e++) {
                int c   = cb + p * 2 + e;
                int seg = c >> 6;             // 0: hi, 1: hi, 2: lo
                int idx = c & 63;
                float val;
                if (isWm) {
                    val = sp[idx * 17 + r];               // Vm[k, i=idx, v=r]
                } else {
                    int f = r * 64 + idx;                 // Vh[k, v=r, j=idx]
                    val = sp[(f >> 4) * 17 + (f & 15)];
                }
                __nv_bfloat16 hi = __float2bfloat16(val);
                hw[e] = (seg == 2)
                    ? __bfloat16_as_ushort(__float2bfloat16(val - __bfloat162float(hi)))
                    : __bfloat16_as_ushort(hi);
            }
            uw[p] = (unsigned)hw[0] | ((unsigned)hw[1] << 16);
        }
        __nv_bfloat16* base = isWm ? g_WmC : g_WhC;
        uint4* dw = reinterpret_cast<uint4*>(base + kv * CW + cb);
        dw[0] = make_uint4(uw[0], uw[1], uw[2],  uw[3]);
        dw[1] = make_uint4(uw[4], uw[5], uw[6],  uw[7]);
        dw[2] = make_uint4(uw[8], uw[9], uw[10], uw[11]);
    }
}

// ============================ GEMM kernel ============================
// CTA = 128 n-rows x 64 kv-cols (4 k). 8 warps, warp = 16 n-rows.
// smem: Xs 128 rows x 400B = 51200; Ws 64 rows x 400B = 25600. Total 76800.
#define SMEM_MAIN 76800
#define NTHR2 256

__device__ __forceinline__ void ldsm_x4(unsigned& r0, unsigned& r1,
                                        unsigned& r2, unsigned& r3,
                                        unsigned addr) {
    asm volatile("ldmatrix.sync.aligned.m8n8.x4.shared.b16 {%0,%1,%2,%3}, [%4];"
        : "=r"(r0), "=r"(r1), "=r"(r2), "=r"(r3) : "r"(addr));
}
__device__ __forceinline__ void mma_bf16(float c[4],
        unsigned a0, unsigned a1, unsigned a2, unsigned a3,
        unsigned b0, unsigned b1) {
    asm volatile(
        "mma.sync.aligned.m16n8k16.row.col.f32.bf16.bf16.f32 "
        "{%0,%1,%2,%3},{%4,%5,%6,%7},{%8,%9},{%0,%1,%2,%3};"
        : "+f"(c[0]), "+f"(c[1]), "+f"(c[2]), "+f"(c[3])
        : "r"(a0), "r"(a1), "r"(a2), "r"(a3), "r"(b0), "r"(b1));
}
__device__ __forceinline__ void sts128(unsigned addr, uint4 v) {
    asm volatile("st.shared.v4.u32 [%0], {%1,%2,%3,%4};"
        :: "r"(addr), "r"(v.x), "r"(v.y), "r"(v.z), "r"(v.w));
}

__global__ void __launch_bounds__(NTHR2, 2)
cin_mma_kernel(float* __restrict__ out)
{
    extern __shared__ __align__(16) unsigned char smem[];
    const unsigned sX = (unsigned)__cvta_generic_to_shared(smem);
    const unsigned sW = sX + 51200u;

    const int tid    = threadIdx.x;
    const int kvtile = blockIdx.x * 64;   // 16 kv-tiles
    const int ntile  = blockIdx.y * 128;  // 16 n-tiles
    const int k0     = blockIdx.x * 4;

    // ---- stage phase A: XaC rows [ntile..+128), WmC rows [kvtile..+64) ----
    {
        const uint4* gx = reinterpret_cast<const uint4*>(g_XaC + ntile * CW);
        #pragma unroll
        for (int e = 0; e < 12; e++) {
            int idx = tid + e * NTHR2;        // 0..3071 (128 rows x 24)
            int row = idx / 24, c16 = idx - row * 24;
            sts128(sX + (unsigned)(row * XROWB + c16 * 16), gx[idx]);
        }
        const uint4* gw = reinterpret_cast<const uint4*>(g_WmC + kvtile * CW);
        #pragma unroll
        for (int e = 0; e < 6; e++) {
            int idx = tid + e * NTHR2;        // 0..1535 (64 rows x 24)
            int row = idx / 24, c16 = idx - row * 24;
            sts128(sW + (unsigned)(row * XROWB + c16 * 16), gw[idx]);
        }
    }
    __syncthreads();

    const int w    = tid >> 5;    // warp 0..7 -> rows w*16..+15
    const int lane = tid & 31;
    const int g    = lane >> 2;
    const int q    = lane & 3;
    const int rA   = w * 16 + g;

    // ldmatrix lane addresses
    const unsigned aBase = sX + (unsigned)((w * 16 + (lane & 15)) * XROWB
                                           + (lane >> 4) * 16);
    const int m = lane >> 3;      // 0..3
    unsigned bBase[4];
    #pragma unroll
    for (int jj = 0; jj < 4; jj++)
        bBase[jj] = sW + (unsigned)((jj * 16 + (m >> 1) * 8 + (lane & 7)) * XROWB
                                    + (m & 1) * 16);

    // ---- GEMM A: cf = Xa * Wm^T ----
    float cf[8][4];
    #pragma unroll
    for (int j = 0; j < 8; j++)
        #pragma unroll
        for (int p = 0; p < 4; p++) cf[j][p] = 0.f;

    #pragma unroll
    for (int ks = 0; ks < 12; ks++) {
        unsigned off = (unsigned)(ks * 32);
        unsigned a0, a1, a2, a3;
        ldsm_x4(a0, a1, a2, a3, aBase + off);
        #pragma unroll
        for (int jj = 0; jj < 4; jj++) {
            unsigned r0, r1, r2, r3;
            ldsm_x4(r0, r1, r2, r3, bBase[jj] + off);
            mma_bf16(cf[2 * jj],     a0, a1, a2, a3, r0, r1);
            mma_bf16(cf[2 * jj + 1], a0, a1, a2, a3, r2, r3);
        }
    }
    __syncthreads();

    // ---- stage phase B: XbC / WhC ----
    {
        const uint4* gx = reinterpret_cast<const uint4*>(g_XbC + ntile * CW);
        #pragma unroll
        for (int e = 0; e < 12; e++) {
            int idx = tid + e * NTHR2;
            int row = idx / 24, c16 = idx - row * 24;
            sts128(sX + (unsigned)(row * XROWB + c16 * 16), gx[idx]);
        }
        const uint4* gw = reinterpret_cast<const uint4*>(g_WhC + kvtile * CW);
        #pragma unroll
        for (int e = 0; e < 6; e++) {
            int idx = tid + e * NTHR2;
            int row = idx / 24, c16 = idx - row * 24;
            sts128(sW + (unsigned)(row * XROWB + c16 * 16), gw[idx]);
        }
    }
    __syncthreads();

    // ---- GEMM B: cq = Xb * Wh^T ----
    float cq[8][4];
    #pragma unroll
    for (int j = 0; j < 8; j++)
        #pragma unroll
        for (int p = 0; p < 4; p++) cq[j][p] = 0.f;

    #pragma unroll
    for (int ks = 0; ks < 12; ks++) {
        unsigned off = (unsigned)(ks * 32);
        unsigned a0, a1, a2, a3;
        ldsm_x4(a0, a1, a2, a3, aBase + off);
        #pragma unroll
        for (int jj = 0; jj < 4; jj++) {
            unsigned r0, r1, r2, r3;
            ldsm_x4(r0, r1, r2, r3, bBase[jj] + off);
            mma_bf16(cq[2 * jj],     a0, a1, a2, a3, r0, r1);
            mma_bf16(cq[2 * jj + 1], a0, a1, a2, a3, r2, r3);
        }
    }

    // ---- dot in registers: out[n,k] = sum_v P*Q (16 cols per k) ----
    float sl[4] = {0.f, 0.f, 0.f, 0.f};
    float sh[4] = {0.f, 0.f, 0.f, 0.f};
    #pragma unroll
    for (int j = 0; j < 8; j++) {
        int kg = j >> 1;
        sl[kg] = fmaf(cf[j][0], cq[j][0], fmaf(cf[j][1], cq[j][1], sl[kg]));
        sh[kg] = fmaf(cf[j][2], cq[j][2], fmaf(cf[j][3], cq[j][3], sh[kg]));
    }
    #pragma unroll
    for (int kg = 0; kg < 4; kg++) {
        sl[kg] += __shfl_xor_sync(0xffffffffu, sl[kg], 1);
        sl[kg] += __shfl_xor_sync(0xffffffffu, sl[kg], 2);
        sh[kg] += __shfl_xor_sync(0xffffffffu, sh[kg], 1);
        sh[kg] += __shfl_xor_sync(0xffffffffu, sh[kg], 2);
    }
    if (q == 0) {
        int n0 = ntile + rA;
        int n1 = n0 + 8;
        #pragma unroll
        for (int kg = 0; kg < 4; kg++) {
            int k = k0 + kg;
            out[(n0 >> 4) * 1024 + k * 16 + (n0 & 15)] = sl[kg];
            out[(n1 >> 4) * 1024 + k * 16 + (n1 & 15)] = sh[kg];
        }
    }
}

extern "C" void kernel_launch(void* const* d_in, const int* in_sizes, int n_in,
                              void* d_out, int out_size) {
    (void)in_sizes; (void)n_in; (void)out_size;
    const float* x0 = (const float*)d_in[0];
    // d_in[1] (x_h) intentionally unused: reference recomputes it from x_0.
    const float* Vm = (const float*)d_in[2];
    const float* Vh = (const float*)d_in[3];
    float* out = (float*)d_out;

    cudaFuncSetAttribute(cin_mma_kernel,
                         cudaFuncAttributeMaxDynamicSharedMemorySize, SMEM_MAIN);

    prep_kernel<<<256, 128>>>(x0, Vm, Vh);
    dim3 grid(16, 16);   // (kv-tiles of 64 cols, n-tiles of 128 rows) = 256 CTAs
    cin_mma_kernel<<<grid, NTHR2, SMEM_MAIN>>>(out);
}

// round 14
// speedup vs baseline: 1.6875x; 1.0388x over previous
#include <cuda_runtime.h>
#include <cuda_bf16.h>

// Problem constants (fixed by setup_inputs):
// x_0  : [128, 64, 16] f32   (d_in[0])
// x_h  : [128, 64, 16] f32   (d_in[1], UNUSED — reference bug recomputes from x_0)
// Vm   : [64, 1, 64, 16] f32 (d_in[2])
// Vh   : [64, 1, 16, 64] f32 (d_in[3])
// out  : [128, 64, 16] f32
//
// out[b,k,d] = sum_v P[n,kv]*Q[n,kv], n = b*16+d, kv = k*16+v
//   P = Xa[2048x64] * Wm^T,  Q = Xb[2048x64] * Wh^T
// bf16 3-term split folded into K=192: A=[hi|lo|hi], B=[whi|whi|wlo].
//
// R14: prep unchanged. GEMM kernel: CTA = 128n x 128kv, ALL four operand
// tiles cp.async'd upfront (200KB smem, 1 CTA/SM, 128 CTAs = single wave),
// ONE barrier, interleaved GEMM A/B mma loop, warp tile 32x32, in-reg dot.

#define CW 192           // composite K width (bf16)
#define NROWS 2048
#define KVROWS 1024
#define XROWB 400        // padded smem row stride in bytes (192 bf16 = 384 + 16 pad)

__device__ __nv_bfloat16 g_XaC[NROWS * CW];
__device__ __nv_bfloat16 g_XbC[NROWS * CW];
__device__ __nv_bfloat16 g_WmC[KVROWS * CW];
__device__ __nv_bfloat16 g_WhC[KVROWS * CW];

// ============================ prep kernel ============================
__global__ void __launch_bounds__(128)
prep_kernel(const float* __restrict__ x0,
            const float* __restrict__ Vm,
            const float* __restrict__ Vh)
{
    __shared__ float sp[64 * 17 + 17];
    const int tid = threadIdx.x;
    const int bid = blockIdx.x;

    const float* src;
    if (bid < 128)      src = x0 + bid * 1024;
    else if (bid < 192) src = Vm + (bid - 128) * 1024;
    else                src = Vh + (bid - 192) * 1024;

    const float4* s4 = reinterpret_cast<const float4*>(src);
    #pragma unroll
    for (int e = 0; e < 2; e++) {
        int f4 = tid + e * 128;
        float4 wv = s4[f4];
        int f = f4 * 4;
        float* dst = &sp[(f >> 4) * 17 + (f & 15)];
        dst[0] = wv.x; dst[1] = wv.y; dst[2] = wv.z; dst[3] = wv.w;
    }
    __syncthreads();

    const int r  = tid >> 3;          // d (X) or v (W), 0..15
    const int cb = (tid & 7) * 24;    // 24 consecutive c per thread

    if (bid < 128) {
        const int n = bid * 16 + r;
        unsigned ua[12], ub[12];
        #pragma unroll
        for (int p = 0; p < 12; p++) {
            unsigned short ha[2], hb[2];
            #pragma unroll
            for (int e = 0; e < 2; e++) {
                int c   = cb + p * 2 + e;
                int seg = c >> 6;             // 0: hi, 1: lo, 2: hi
                int idx = c & 63;
                float va = sp[idx * 17 + r];
                __nv_bfloat16 hia = __float2bfloat16(va);
                ha[e] = (seg == 1)
                    ? __bfloat16_as_ushort(__float2bfloat16(va - __bfloat162float(hia)))
                    : __bfloat16_as_ushort(hia);
                int f = r * 64 + idx;
                float vb = sp[(f >> 4) * 17 + (f & 15)];
                __nv_bfloat16 hib = __float2bfloat16(vb);
                hb[e] = (seg == 1)
                    ? __bfloat16_as_ushort(__float2bfloat16(vb - __bfloat162float(hib)))
                    : __bfloat16_as_ushort(hib);
            }
            ua[p] = (unsigned)ha[0] | ((unsigned)ha[1] << 16);
            ub[p] = (unsigned)hb[0] | ((unsigned)hb[1] << 16);
        }
        uint4* da = reinterpret_cast<uint4*>(g_XaC + n * CW + cb);
        da[0] = make_uint4(ua[0], ua[1], ua[2],  ua[3]);
        da[1] = make_uint4(ua[4], ua[5], ua[6],  ua[7]);
        da[2] = make_uint4(ua[8], ua[9], ua[10], ua[11]);
        uint4* db = reinterpret_cast<uint4*>(g_XbC + n * CW + cb);
        db[0] = make_uint4(ub[0], ub[1], ub[2],  ub[3]);
        db[1] = make_uint4(ub[4], ub[5], ub[6],  ub[7]);
        db[2] = make_uint4(ub[8], ub[9], ub[10], ub[11]);
    } else {
        const bool isWm = bid < 192;
        const int k  = isWm ? (bid - 128) : (bid - 192);
        const int kv = k * 16 + r;
        unsigned uw[12];
        #pragma unroll
        for (int p = 0; p < 12; p++) {
            unsigned short hw[2];
            #pragma unroll
            for (int e = 0; e < 2; e++) {
                int c   = cb + p * 2 + e;
                int seg = c >> 6;             // 0: hi, 1: hi, 2: lo
                int idx = c & 63;
                float val;
                if (isWm) val = sp[idx * 17 + r];
                else { int f = r * 64 + idx; val = sp[(f >> 4) * 17 + (f & 15)]; }
                __nv_bfloat16 hi = __float2bfloat16(val);
                hw[e] = (seg == 2)
                    ? __bfloat16_as_ushort(__float2bfloat16(val - __bfloat162float(hi)))
                    : __bfloat16_as_ushort(hi);
            }
            uw[p] = (unsigned)hw[0] | ((unsigned)hw[1] << 16);
        }
        __nv_bfloat16* base = isWm ? g_WmC : g_WhC;
        uint4* dw = reinterpret_cast<uint4*>(base + kv * CW + cb);
        dw[0] = make_uint4(uw[0], uw[1], uw[2],  uw[3]);
        dw[1] = make_uint4(uw[4], uw[5], uw[6],  uw[7]);
        dw[2] = make_uint4(uw[8], uw[9], uw[10], uw[11]);
    }
}

// ============================ GEMM kernel ============================
// CTA = 128 n-rows x 128 kv-cols. 16 warps (512 thr), warp tile 32n x 32kv.
// smem: Xa 51200 | Xb 51200 | Wm 51200 | Wh 51200 = 204800 B. 1 CTA/SM.
#define SMEM_MAIN 204800
#define NTHR2 512
#define RSZ 51200u

__device__ __forceinline__ void ldsm_x4(unsigned& r0, unsigned& r1,
                                        unsigned& r2, unsigned& r3,
                                        unsigned addr) {
    asm volatile("ldmatrix.sync.aligned.m8n8.x4.shared.b16 {%0,%1,%2,%3}, [%4];"
        : "=r"(r0), "=r"(r1), "=r"(r2), "=r"(r3) : "r"(addr));
}
__device__ __forceinline__ void mma_bf16(float c[4],
        unsigned a0, unsigned a1, unsigned a2, unsigned a3,
        unsigned b0, unsigned b1) {
    asm volatile(
        "mma.sync.aligned.m16n8k16.row.col.f32.bf16.bf16.f32 "
        "{%0,%1,%2,%3},{%4,%5,%6,%7},{%8,%9},{%0,%1,%2,%3};"
        : "+f"(c[0]), "+f"(c[1]), "+f"(c[2]), "+f"(c[3])
        : "r"(a0), "r"(a1), "r"(a2), "r"(a3), "r"(b0), "r"(b1));
}
__device__ __forceinline__ void cp16(unsigned saddr, const void* gaddr) {
    asm volatile("cp.async.cg.shared.global [%0], [%1], 16;"
        :: "r"(saddr), "l"(gaddr));
}

__global__ void __launch_bounds__(NTHR2, 1)
cin_mma_kernel(float* __restrict__ out)
{
    extern __shared__ __align__(16) unsigned char smem[];
    const unsigned sXa = (unsigned)__cvta_generic_to_shared(smem);
    const unsigned sXb = sXa + RSZ;
    const unsigned sWm = sXa + 2u * RSZ;
    const unsigned sWh = sXa + 3u * RSZ;

    const int tid    = threadIdx.x;
    const int kvtile = blockIdx.x * 128;  // 8 kv-tiles (8 k each)
    const int ntile  = blockIdx.y * 128;  // 16 n-tiles
    const int k0     = blockIdx.x * 8;

    // ---- stage all four regions with cp.async (24 uint4 per row) ----
    {
        const uint4* gXa = reinterpret_cast<const uint4*>(g_XaC + ntile * CW);
        const uint4* gXb = reinterpret_cast<const uint4*>(g_XbC + ntile * CW);
        const uint4* gWm = reinterpret_cast<const uint4*>(g_WmC + kvtile * CW);
        const uint4* gWh = reinterpret_cast<const uint4*>(g_WhC + kvtile * CW);
        #pragma unroll
        for (int e = 0; e < 6; e++) {
            int idx = tid + e * NTHR2;          // 0..3071 (128 rows x 24)
            int row = idx / 24, c16 = idx - row * 24;
            unsigned soff = (unsigned)(row * XROWB + c16 * 16);
            cp16(sXa + soff, gXa + idx);
            cp16(sXb + soff, gXb + idx);
            cp16(sWm + soff, gWm + idx);
            cp16(sWh + soff, gWh + idx);
        }
        asm volatile("cp.async.commit_group;");
        asm volatile("cp.async.wait_group 0;");
    }
    __syncthreads();

    // warp w: nw = w&3 (rows nw*32), kw = w>>2 (cols kw*32)
    const int w    = tid >> 5;
    const int lane = tid & 31;
    const int nw   = w & 3;
    const int kw   = w >> 2;
    const int g    = lane >> 2;
    const int q    = lane & 3;
    const int m    = lane >> 3;

    // A-frag lane addresses (m16k16 x4), two m-blocks per warp
    unsigned aA[2], aB[2];
    #pragma unroll
    for (int mi = 0; mi < 2; mi++) {
        unsigned off = (unsigned)((nw * 32 + mi * 16 + (lane & 15)) * XROWB
                                  + (lane >> 4) * 16);
        aA[mi] = sXa + off;
        aB[mi] = sXb + off;
    }
    // B-frag lane addresses (two 16-col blocks per warp)
    unsigned bA[2], bB[2];
    #pragma unroll
    for (int bi = 0; bi < 2; bi++) {
        unsigned off = (unsigned)((kw * 32 + bi * 16 + (m >> 1) * 8 + (lane & 7)) * XROWB
                                  + (m & 1) * 16);
        bA[bi] = sWm + off;
        bB[bi] = sWh + off;
    }

    // accumulators: cf/cq [m-block][n8-block][frag]
    float cf[2][4][4], cq[2][4][4];
    #pragma unroll
    for (int mi = 0; mi < 2; mi++)
        #pragma unroll
        for (int nj = 0; nj < 4; nj++)
            #pragma unroll
            for (int p = 0; p < 4; p++) { cf[mi][nj][p] = 0.f; cq[mi][nj][p] = 0.f; }

    // ---- single interleaved mainloop over K=192 (12 steps of 16) ----
    #pragma unroll
    for (int ks = 0; ks < 12; ks++) {
        const unsigned off = (unsigned)(ks * 32);
        unsigned xa0[2], xa1[2], xa2[2], xa3[2];
        unsigned xb0[2], xb1[2], xb2[2], xb3[2];
        #pragma unroll
        for (int mi = 0; mi < 2; mi++) {
            ldsm_x4(xa0[mi], xa1[mi], xa2[mi], xa3[mi], aA[mi] + off);
            ldsm_x4(xb0[mi], xb1[mi], xb2[mi], xb3[mi], aB[mi] + off);
        }
        #pragma unroll
        for (int bi = 0; bi < 2; bi++) {
            unsigned wa0, wa1, wa2, wa3, wb0, wb1, wb2, wb3;
            ldsm_x4(wa0, wa1, wa2, wa3, bA[bi] + off);
            ldsm_x4(wb0, wb1, wb2, wb3, bB[bi] + off);
            #pragma unroll
            for (int mi = 0; mi < 2; mi++) {
                mma_bf16(cf[mi][2 * bi],     xa0[mi], xa1[mi], xa2[mi], xa3[mi], wa0, wa1);
                mma_bf16(cf[mi][2 * bi + 1], xa0[mi], xa1[mi], xa2[mi], xa3[mi], wa2, wa3);
                mma_bf16(cq[mi][2 * bi],     xb0[mi], xb1[mi], xb2[mi], xb3[mi], wb0, wb1);
                mma_bf16(cq[mi][2 * bi + 1], xb0[mi], xb1[mi], xb2[mi], xb3[mi], wb2, wb3);
            }
        }
    }

    // ---- in-register dot over v, reduce over q via shfl ----
    // col of cq[mi][nj][0/1] = kw*32 + nj*8 + 2q (+1); k_local = kw*2 + (nj>>1)
    float sl[2][2], sh[2][2];
    #pragma unroll
    for (int mi = 0; mi < 2; mi++)
        #pragma unroll
        for (int kx = 0; kx < 2; kx++) { sl[mi][kx] = 0.f; sh[mi][kx] = 0.f; }
    #pragma unroll
    for (int mi = 0; mi < 2; mi++)
        #pragma unroll
        for (int nj = 0; nj < 4; nj++) {
            int kx = nj >> 1;
            sl[mi][kx] = fmaf(cf[mi][nj][0], cq[mi][nj][0],
                         fmaf(cf[mi][nj][1], cq[mi][nj][1], sl[mi][kx]));
            sh[mi][kx] = fmaf(cf[mi][nj][2], cq[mi][nj][2],
                         fmaf(cf[mi][nj][3], cq[mi][nj][3], sh[mi][kx]));
        }
    #pragma unroll
    for (int mi = 0; mi < 2; mi++)
        #pragma unroll
        for (int kx = 0; kx < 2; kx++) {
            sl[mi][kx] += __shfl_xor_sync(0xffffffffu, sl[mi][kx], 1);
            sl[mi][kx] += __shfl_xor_sync(0xffffffffu, sl[mi][kx], 2);
            sh[mi][kx] += __shfl_xor_sync(0xffffffffu, sh[mi][kx], 1);
            sh[mi][kx] += __shfl_xor_sync(0xffffffffu, sh[mi][kx], 2);
        }
    if (q == 0) {
        #pragma unroll
        for (int mi = 0; mi < 2; mi++) {
            int n0 = ntile + nw * 32 + mi * 16 + g;
            int n1 = n0 + 8;
            #pragma unroll
            for (int kx = 0; kx < 2; kx++) {
                int k = k0 + kw * 2 + kx;
                out[(n0 >> 4) * 1024 + k * 16 + (n0 & 15)] = sl[mi][kx];
                out[(n1 >> 4) * 1024 + k * 16 + (n1 & 15)] = sh[mi][kx];
            }
        }
    }
}

extern "C" void kernel_launch(void* const* d_in, const int* in_sizes, int n_in,
                              void* d_out, int out_size) {
    (void)in_sizes; (void)n_in; (void)out_size;
    const float* x0 = (const float*)d_in[0];
    // d_in[1] (x_h) intentionally unused: reference recomputes it from x_0.
    const float* Vm = (const float*)d_in[2];
    const float* Vh = (const float*)d_in[3];
    float* out = (float*)d_out;

    cudaFuncSetAttribute(cin_mma_kernel,
                         cudaFuncAttributeMaxDynamicSharedMemorySize, SMEM_MAIN);

    prep_kernel<<<256, 128>>>(x0, Vm, Vh);
    dim3 grid(8, 16);    // (kv-tiles of 128 cols, n-tiles of 128 rows) = 128 CTAs
    cin_mma_kernel<<<grid, NTHR2, SMEM_MAIN>>>(out);
}